// round 1
// baseline (speedup 1.0000x reference)
#include <cuda_runtime.h>
#include <math.h>

#define NMAX 8192
#define KNB 32
#define CUTOFF2 100.0f
#define CAP 256           // compacted in-cutoff candidates per node (expected ~34)
#define WARPS_PER_BLK 8

// packed positions: (x, y, z, x^2+y^2+z^2)
__device__ float4 g_p4[NMAX];

__global__ void prep_kernel(const float* __restrict__ pos, int N) {
    int i = blockIdx.x * blockDim.x + threadIdx.x;
    if (i < N) {
        float x = pos[3 * i + 0];
        float y = pos[3 * i + 1];
        float z = pos[3 * i + 2];
        g_p4[i] = make_float4(x, y, z, x * x + y * y + z * z);
    }
}

// map float -> monotonically ordered unsigned (handles tiny negative d2 robustly)
__device__ __forceinline__ unsigned f2ord(float f) {
    unsigned u = __float_as_uint(f);
    return (u & 0x80000000u) ? ~u : (u | 0x80000000u);
}

__global__ void radius_kernel(const int* __restrict__ batch,
                              float* __restrict__ out, int N) {
    __shared__ float sd2[WARPS_PER_BLK][CAP];
    __shared__ int   sjj[WARPS_PER_BLK][CAP];

    const int w    = threadIdx.x >> 5;
    const int lane = threadIdx.x & 31;
    const int i    = blockIdx.x * WARPS_PER_BLK + w;
    if (i >= N) return;

    const float4 pi = g_p4[i];
    const int b = batch[i];

    // batch segment [s, e) via binary search (batch is sorted)
    int s = 0, e = 0;
    if (lane == 0) {
        int lo = 0, hi = N;
        while (lo < hi) { int m = (lo + hi) >> 1; if (batch[m] <  b) lo = m + 1; else hi = m; }
        s = lo;
        lo = 0; hi = N;
        while (lo < hi) { int m = (lo + hi) >> 1; if (batch[m] <= b) lo = m + 1; else hi = m; }
        e = lo;
    }
    s = __shfl_sync(0xffffffffu, s, 0);
    e = __shfl_sync(0xffffffffu, e, 0);

    // Phase A: scan segment, compact in-cutoff candidates (gram-trick d2, like ref)
    int cnt = 0;
    for (int base = s; base < e; base += 32) {
        int j = base + lane;
        bool pass = false;
        float d2 = 0.0f;
        if (j < e && j != i) {
            float4 pj = g_p4[j];
            float dot = pi.x * pj.x + pi.y * pj.y + pi.z * pj.z;
            d2 = pi.w + pj.w - 2.0f * dot;
            pass = (d2 <= CUTOFF2);
        }
        unsigned m = __ballot_sync(0xffffffffu, pass);
        if (pass) {
            int idx = cnt + __popc(m & ((1u << lane) - 1u));
            if (idx < CAP) { sd2[w][idx] = d2; sjj[w][idx] = j; }
        }
        cnt += __popc(m);
    }
    if (cnt > CAP) cnt = CAP;
    __syncwarp();

    const long long E    = (long long)N * KNB + N;
    float* __restrict__ orow = out;
    float* __restrict__ ocol = out + E;
    float* __restrict__ owt  = out + 2 * E;
    float* __restrict__ omk  = out + 3 * E;
    const long long bo = (long long)i * KNB;

    // col is always i; padded slots (k >= cnt): row=0, w=0, mask=0
    {
        int k = lane;  // KNB == 32 == warp size
        ocol[bo + k] = (float)i;
        if (k >= cnt) { orow[bo + k] = 0.0f; owt[bo + k] = 0.0f; omk[bo + k] = 0.0f; }
    }

    // Phase B: rank-by-counting over compacted list; rank == output slot.
    // key = (d2 asc, j asc) — exactly top_k(-d2) ordering.
    for (int c = lane; c < cnt; c += 32) {
        unsigned long long key =
            ((unsigned long long)f2ord(sd2[w][c]) << 32) | (unsigned)sjj[w][c];
        int rank = 0;
        for (int t = 0; t < cnt; t++) {
            unsigned long long kt =
                ((unsigned long long)f2ord(sd2[w][t]) << 32) | (unsigned)sjj[w][t];
            rank += (kt < key);
        }
        if (rank < KNB) {
            int j = sjj[w][c];
            float4 pj = g_p4[j];
            float dx = pj.x - pi.x, dy = pj.y - pi.y, dz = pj.z - pi.z;
            float sq = dx * dx + dy * dy + dz * dz;
            float wt = (sq > 0.0f) ? sqrtf(sq) : 0.0f;  // exact Euclidean, like ref weight
            orow[bo + rank] = (float)j;
            owt [bo + rank] = wt;
            omk [bo + rank] = 1.0f;
        }
    }

    // self-loop at N*K + i
    if (lane == 0) {
        long long si = (long long)N * KNB + i;
        orow[si] = (float)i;
        ocol[si] = (float)i;
        owt [si] = 0.0f;
        omk [si] = 1.0f;
    }
}

extern "C" void kernel_launch(void* const* d_in, const int* in_sizes, int n_in,
                              void* d_out, int out_size) {
    const float* pos  = (const float*)d_in[0];
    const int*   batch = (const int*)d_in[1];
    float* out = (float*)d_out;
    int N = in_sizes[0] / 3;   // 8192

    prep_kernel<<<(N + 255) / 256, 256>>>(pos, N);
    radius_kernel<<<(N + WARPS_PER_BLK - 1) / WARPS_PER_BLK, WARPS_PER_BLK * 32>>>(batch, out, N);
}

// round 3
// speedup vs baseline: 1.0875x; 1.0875x over previous
#include <cuda_runtime.h>
#include <math.h>

#define NMAX 8192
#define KNB 32
#define CUTOFF2 100.0f
#define CAP 192
#define WARPS_PER_BLK 8
#define NCELL 5
#define NBINS (8 * NCELL * NCELL * NCELL)   // 1000

// scratch (device globals — no allocation allowed)
__device__ float4 g_tp4[NMAX];     // unsorted packed pos (x,y,z,|p|^2)
__device__ int    g_tbin[NMAX];    // bin per original point
__device__ int    g_start[NBINS + 1];
__device__ int    g_cur[NBINS];
__device__ float4 g_sp4[NMAX];     // cell-sorted packed pos
__device__ int    g_sidx[NMAX];    // sorted slot -> original index
__device__ int    g_sbin[NMAX];    // sorted slot -> bin

__device__ __forceinline__ unsigned f2ord(float f) {
    unsigned u = __float_as_uint(f);
    return (u & 0x80000000u) ? ~u : (u | 0x80000000u);
}

__global__ void prep_kernel(const float* __restrict__ pos,
                            const int* __restrict__ batch, int N) {
    int i = blockIdx.x * blockDim.x + threadIdx.x;
    if (i >= N) return;
    float x = pos[3 * i + 0];
    float y = pos[3 * i + 1];
    float z = pos[3 * i + 2];
    g_tp4[i] = make_float4(x, y, z, x * x + y * y + z * z);
    int cx = min(NCELL - 1, max(0, (int)(x * 0.1f)));
    int cy = min(NCELL - 1, max(0, (int)(y * 0.1f)));
    int cz = min(NCELL - 1, max(0, (int)(z * 0.1f)));
    g_tbin[i] = batch[i] * (NCELL * NCELL * NCELL) + (cz * NCELL + cy) * NCELL + cx;
}

// single block: zero hist + shared-atomic histogram + exclusive scan
__global__ void hist_scan_kernel(int N) {
    __shared__ int hist[1024];
    __shared__ int buf[2][1024];
    int t = threadIdx.x;
    hist[t] = 0;
    __syncthreads();
    for (int p = t; p < N; p += 1024) atomicAdd(&hist[g_tbin[p]], 1);
    __syncthreads();
    int val = hist[t];                 // bins >= NBINS stay 0
    buf[0][t] = val;
    __syncthreads();
    int cur = 0;
    for (int off = 1; off < 1024; off <<= 1) {
        int nxt = cur ^ 1;
        int v = buf[cur][t];
        if (t >= off) v += buf[cur][t - off];
        buf[nxt][t] = v;
        __syncthreads();
        cur = nxt;
    }
    int excl = buf[cur][t] - val;      // exclusive prefix sum
    if (t <= NBINS) g_start[t] = excl; // g_start[NBINS] == N
    if (t < NBINS)  g_cur[t]   = excl;
}

__global__ void scatter_kernel(int N) {
    int i = blockIdx.x * blockDim.x + threadIdx.x;
    if (i >= N) return;
    int bin = g_tbin[i];
    int p = atomicAdd(&g_cur[bin], 1);
    g_sp4[p]  = g_tp4[i];
    g_sidx[p] = i;
    g_sbin[p] = bin;
}

__global__ void radius_kernel(float* __restrict__ out, int N) {
    __shared__ unsigned long long skey[WARPS_PER_BLK][CAP];

    const int w    = threadIdx.x >> 5;
    const int lane = threadIdx.x & 31;
    const int u    = blockIdx.x * WARPS_PER_BLK + w;   // sorted slot
    if (u >= N) return;

    const float4 pi = g_sp4[u];
    const int i   = g_sidx[u];
    const int bin = g_sbin[u];
    const int c     = bin % (NCELL * NCELL * NCELL);
    const int bbase = bin - c;
    const int cx = c % NCELL;
    const int cy = (c / NCELL) % NCELL;
    const int cz = c / (NCELL * NCELL);
    const int x0 = max(cx - 1, 0), x1 = min(cx + 1, NCELL - 1);
    const int y0 = max(cy - 1, 0), y1 = min(cy + 1, NCELL - 1);
    const int z0 = max(cz - 1, 0), z1 = min(cz + 1, NCELL - 1);

    // Phase A: scan <=9 contiguous bin ranges, compact packed keys
    int cnt = 0;
    for (int z = z0; z <= z1; z++) {
        for (int y = y0; y <= y1; y++) {
            int blo = bbase + (z * NCELL + y) * NCELL + x0;
            int s = g_start[blo];
            int e = g_start[blo + (x1 - x0) + 1];
            for (int base = s; base < e; base += 32) {
                int t = base + lane;
                bool pass = false;
                float d2 = 0.0f;
                if (t < e && t != u) {
                    float4 pj = g_sp4[t];
                    float dot = pi.x * pj.x + pi.y * pj.y + pi.z * pj.z;
                    d2 = pi.w + pj.w - 2.0f * dot;   // gram-trick, like reference
                    pass = (d2 <= CUTOFF2);
                }
                unsigned m = __ballot_sync(0xffffffffu, pass);
                if (pass) {
                    int idx = cnt + __popc(m & ((1u << lane) - 1u));
                    if (idx < CAP) {
                        int j = g_sidx[t];   // original index = tie-break key
                        skey[w][idx] = ((unsigned long long)f2ord(d2) << 32) | (unsigned)j;
                    }
                }
                cnt += __popc(m);
            }
        }
    }
    if (cnt > CAP) cnt = CAP;
    __syncwarp();

    const long long E = (long long)N * KNB + N;
    float* __restrict__ orow = out;
    float* __restrict__ ocol = out + E;
    float* __restrict__ owt  = out + 2 * E;
    float* __restrict__ omk  = out + 3 * E;
    const long long bo = (long long)i * KNB;

    // col is always i; padded slots (k >= cnt): row=0, w=0, mask=0
    {
        int k = lane;   // KNB == 32
        ocol[bo + k] = (float)i;
        if (k >= cnt) { orow[bo + k] = 0.0f; owt[bo + k] = 0.0f; omk[bo + k] = 0.0f; }
    }

    // Phase B: rank-by-counting; rank == output slot (== top_k order)
    for (int cc = lane; cc < cnt; cc += 32) {
        unsigned long long key = skey[w][cc];
        int rank = 0;
        for (int t = 0; t < cnt; t++) rank += (skey[w][t] < key);
        if (rank < KNB) {
            int j = (int)(unsigned)(key & 0xffffffffu);
            float4 pj = g_tp4[j];
            float dx = pj.x - pi.x, dy = pj.y - pi.y, dz = pj.z - pi.z;
            float sq = dx * dx + dy * dy + dz * dz;
            float wt = (sq > 0.0f) ? sqrtf(sq) : 0.0f;
            orow[bo + rank] = (float)j;
            owt [bo + rank] = wt;
            omk [bo + rank] = 1.0f;
        }
    }

    // self-loop at N*K + i
    if (lane == 0) {
        long long si = (long long)N * KNB + i;
        orow[si] = (float)i;
        ocol[si] = (float)i;
        owt [si] = 0.0f;
        omk [si] = 1.0f;
    }
}

extern "C" void kernel_launch(void* const* d_in, const int* in_sizes, int n_in,
                              void* d_out, int out_size) {
    const float* pos   = (const float*)d_in[0];
    const int*   batch = (const int*)d_in[1];
    float* out = (float*)d_out;
    int N = in_sizes[0] / 3;   // 8192

    prep_kernel<<<(N + 255) / 256, 256>>>(pos, batch, N);
    hist_scan_kernel<<<1, 1024>>>(N);
    scatter_kernel<<<(N + 255) / 256, 256>>>(N);
    radius_kernel<<<(N + WARPS_PER_BLK - 1) / WARPS_PER_BLK, WARPS_PER_BLK * 32>>>(out, N);
}